// round 1
// baseline (speedup 1.0000x reference)
#include <cuda_runtime.h>
#include <math.h>

#define BB  4
#define CC  256
#define ACK 64      // attn channels
#define NN  4096    // W*H

// -------- device-global scratch (no runtime allocation allowed) --------
__device__ float g_q[(size_t)BB * ACK * NN];           //  4 MB  [b][c][i]
__device__ float g_k[(size_t)BB * ACK * NN];           //  4 MB  [b][c][j]
__device__ float g_v[(size_t)BB * CC  * NN];           // 16 MB  [b][c][j]
__device__ float g_P[(size_t)BB * NN  * NN];           // 256 MB [b][j][i]  (scores, then probs)

// ---------------------------------------------------------------------
// Kernel 1: q/k/v channel GEMMs (1x1 convs). Early-exits when gamma==0.
// ---------------------------------------------------------------------
__global__ void qkv_kernel(const float* __restrict__ x,
                           const float* __restrict__ Wq, const float* __restrict__ bq,
                           const float* __restrict__ Wk, const float* __restrict__ bk,
                           const float* __restrict__ Wv, const float* __restrict__ bv,
                           const float* __restrict__ gamma)
{
    if (gamma[0] == 0.0f) return;   // gamma*A + x == x : skip all attention work
    const int OTOT = 2 * ACK + CC;  // 384 output channels total
    const int total = BB * OTOT * NN;
    for (int idx = blockIdx.x * blockDim.x + threadIdx.x; idx < total;
         idx += gridDim.x * blockDim.x) {
        int b = idx / (OTOT * NN);
        int r = idx % (OTOT * NN);
        int o = r / NN;
        int n = r % NN;
        const float* w; float bias; float* dst;
        if (o < ACK)            { w = Wq + o * CC;            bias = bq[o];
                                  dst = g_q + ((size_t)b * ACK + o) * NN + n; }
        else if (o < 2 * ACK)   { int oo = o - ACK;   w = Wk + oo * CC; bias = bk[oo];
                                  dst = g_k + ((size_t)b * ACK + oo) * NN + n; }
        else                    { int oo = o - 2*ACK; w = Wv + oo * CC; bias = bv[oo];
                                  dst = g_v + ((size_t)b * CC + oo) * NN + n; }
        const float* xb = x + (size_t)b * CC * NN + n;
        float acc = bias;
        #pragma unroll 8
        for (int c = 0; c < CC; c++) acc += w[c] * xb[(size_t)c * NN];
        *dst = acc;
    }
}

// ---------------------------------------------------------------------
// Kernel 2: scores, stored TRANSPOSED: P[b][j][i] = sum_c q[b,c,i]*k[b,c,j]
// so that the axis=1 softmax (over i) becomes a contiguous row reduction.
// 32x32 output tiles, K=64 staged through shared memory.
// ---------------------------------------------------------------------
__global__ void score_kernel(const float* __restrict__ gamma)
{
    if (gamma[0] == 0.0f) return;
    __shared__ float qs[ACK][32];
    __shared__ float ks[ACK][32];
    const int tiles = NN / 32;                 // 128
    const int ntiles = BB * tiles * tiles;     // 65536
    int tx = threadIdx.x & 31, ty = threadIdx.x >> 5;   // ty in [0,8)
    for (int t = blockIdx.x; t < ntiles; t += gridDim.x) {
        int b  = t / (tiles * tiles);
        int rr = t % (tiles * tiles);
        int jt = rr / tiles, it = rr % tiles;
        int i0 = it * 32, j0 = jt * 32;
        for (int c = ty; c < ACK; c += 8) {
            qs[c][tx] = g_q[((size_t)b * ACK + c) * NN + i0 + tx];
            ks[c][tx] = g_k[((size_t)b * ACK + c) * NN + j0 + tx];
        }
        __syncthreads();
        float acc[4] = {0.f, 0.f, 0.f, 0.f};
        for (int c = 0; c < ACK; c++) {
            float qv = qs[c][tx];
            #pragma unroll
            for (int s = 0; s < 4; s++) acc[s] += qv * ks[c][ty + 8 * s];
        }
        float* P = g_P + (size_t)b * NN * NN;
        #pragma unroll
        for (int s = 0; s < 4; s++)
            P[(size_t)(j0 + ty + 8 * s) * NN + i0 + tx] = acc[s];
        __syncthreads();
    }
}

// ---------------------------------------------------------------------
// Kernel 3: softmax over i (axis=1 of attn) == contiguous rows of P[b][j][:]
// ---------------------------------------------------------------------
__global__ void softmax_kernel(const float* __restrict__ gamma)
{
    if (gamma[0] == 0.0f) return;
    __shared__ float red[256];
    const int rows = BB * NN;
    for (int row = blockIdx.x; row < rows; row += gridDim.x) {
        float* p = g_P + (size_t)row * NN;
        float m = -INFINITY;
        for (int i = threadIdx.x; i < NN; i += 256) m = fmaxf(m, p[i]);
        red[threadIdx.x] = m; __syncthreads();
        for (int s = 128; s > 0; s >>= 1) {
            if (threadIdx.x < s) red[threadIdx.x] = fmaxf(red[threadIdx.x], red[threadIdx.x + s]);
            __syncthreads();
        }
        m = red[0]; __syncthreads();
        float sum = 0.f;
        for (int i = threadIdx.x; i < NN; i += 256) {
            float e = expf(p[i] - m);
            p[i] = e; sum += e;
        }
        red[threadIdx.x] = sum; __syncthreads();
        for (int s = 128; s > 0; s >>= 1) {
            if (threadIdx.x < s) red[threadIdx.x] += red[threadIdx.x + s];
            __syncthreads();
        }
        float inv = 1.0f / red[0]; __syncthreads();
        for (int i = threadIdx.x; i < NN; i += 256) p[i] *= inv;
    }
}

// ---------------------------------------------------------------------
// Kernel 4: out[b,c,i] = gamma * sum_j P[b,j,i] * v[b,c,j] + x[b,c,i]
// gamma==0 fast path: vectorized copy out = x.
// ---------------------------------------------------------------------
__global__ void out_kernel(const float* __restrict__ x,
                           const float* __restrict__ gamma,
                           float* __restrict__ out)
{
    float g = gamma[0];
    if (g == 0.0f) {
        const float4* x4 = (const float4*)x;
        float4*       o4 = (float4*)out;
        const int total4 = BB * CC * NN / 4;   // 1,048,576
        for (int idx = blockIdx.x * blockDim.x + threadIdx.x; idx < total4;
             idx += gridDim.x * blockDim.x)
            o4[idx] = x4[idx];
        return;
    }
    __shared__ float vs[32][32];
    __shared__ float ps[32][33];
    const int tilesC = CC / 32, tilesI = NN / 32;
    const int ntiles = BB * tilesC * tilesI;   // 4096
    int tx = threadIdx.x & 31, ty = threadIdx.x >> 5;
    for (int t = blockIdx.x; t < ntiles; t += gridDim.x) {
        int b  = t / (tilesC * tilesI);
        int rr = t % (tilesC * tilesI);
        int ct = rr / tilesI, it = rr % tilesI;
        int c0 = ct * 32, i0 = it * 32;
        float acc[4] = {0.f, 0.f, 0.f, 0.f};
        for (int j0 = 0; j0 < NN; j0 += 32) {
            for (int rl = ty; rl < 32; rl += 8) {
                vs[rl][tx] = g_v[((size_t)b * CC + c0 + rl) * NN + j0 + tx];
                ps[rl][tx] = g_P[((size_t)b * NN + j0 + rl) * NN + i0 + tx];
            }
            __syncthreads();
            #pragma unroll
            for (int jj = 0; jj < 32; jj++) {
                float pv = ps[jj][tx];
                #pragma unroll
                for (int s = 0; s < 4; s++) acc[s] += vs[ty + 8 * s][jj] * pv;
            }
            __syncthreads();
        }
        #pragma unroll
        for (int s = 0; s < 4; s++) {
            size_t oidx = ((size_t)b * CC + c0 + ty + 8 * s) * NN + i0 + tx;
            out[oidx] = g * acc[s] + x[oidx];
        }
    }
}

// ---------------------------------------------------------------------
extern "C" void kernel_launch(void* const* d_in, const int* in_sizes, int n_in,
                              void* d_out, int out_size)
{
    const float* x     = (const float*)d_in[0];
    const float* Wq    = (const float*)d_in[1];
    const float* bq    = (const float*)d_in[2];
    const float* Wk    = (const float*)d_in[3];
    const float* bk    = (const float*)d_in[4];
    const float* Wv    = (const float*)d_in[5];
    const float* bv    = (const float*)d_in[6];
    const float* gamma = (const float*)d_in[7];
    float* out = (float*)d_out;

    qkv_kernel    <<<2048, 256>>>(x, Wq, bq, Wk, bk, Wv, bv, gamma);
    score_kernel  <<<2048, 256>>>(gamma);
    softmax_kernel<<<2048, 256>>>(gamma);
    out_kernel    <<<2048, 256>>>(x, gamma, out);
}

// round 2
// speedup vs baseline: 1.1970x; 1.1970x over previous
#include <cuda_runtime.h>
#include <math.h>

#define BB  4
#define CC  256
#define ACK 64      // attn channels
#define NN  4096    // W*H

// -------- device-global scratch (no runtime allocation allowed) --------
__device__ float g_v[(size_t)BB * CC * NN];            //  16 MB  [b][c][j]
__device__ float g_P[(size_t)BB * NN * NN];            // 256 MB  [b][j][i]  probs, transposed

// ---------------------------------------------------------------------
// Kernel A (heavy path only; early-exits when gamma==0):
// For each (b, j-tile of 32 key columns):
//   - recompute k[64][32] and v[256][32] from x (v written to g_v)
//   - loop i-tiles: recompute q[64][32] from x, compute scores,
//     write raw scores to g_P[b][j][i], track per-row max
//   - pass 2: exp + row sum over the (L2-hot) written row
//   - pass 3: scale by 1/sum  -> g_P holds softmax(axis=i) probabilities
// ---------------------------------------------------------------------
__global__ void fused_ps_kernel(const float* __restrict__ x,
                                const float* __restrict__ Wq, const float* __restrict__ bq,
                                const float* __restrict__ Wk, const float* __restrict__ bk,
                                const float* __restrict__ Wv, const float* __restrict__ bv,
                                const float* __restrict__ gamma)
{
    if (gamma[0] == 0.0f) return;   // gamma*A + x == x : all attention work dead

    __shared__ float xs[128][32];   // 16 KB : half of channels of one 32-col slab
    __shared__ float kt[ACK][32];   //  8 KB
    __shared__ float qt[ACK][32];   //  8 KB
    __shared__ float rowmax[32];
    __shared__ float rowsum[32];

    const int t    = threadIdx.x;
    const int tx   = t & 31;
    const int wid  = t >> 5;        // 0..7
    const int c64  = t & 63;
    const int part = t >> 6;        // 0..3

    const int ntiles = BB * (NN / 32);   // 512
    for (int tile = blockIdx.x; tile < ntiles; tile += gridDim.x) {
        int b  = tile >> 7;
        int jt = tile & 127;
        int j0 = jt * 32;
        const float* xb = x + (size_t)b * CC * NN;
        float* Pb = g_P + (size_t)b * NN * NN;

        // ---- k tile + v tile from x columns [j0, j0+32) ----
        float vacc[32];
        #pragma unroll
        for (int u = 0; u < 32; u++) vacc[u] = bv[t];
        float kacc[8];
        #pragma unroll
        for (int u = 0; u < 8; u++) kacc[u] = bk[c64];

        for (int half = 0; half < 2; half++) {
            __syncthreads();
            for (int r = wid; r < 128; r += 8)
                xs[r][tx] = xb[(size_t)(half * 128 + r) * NN + j0 + tx];
            __syncthreads();
            for (int r = 0; r < 128; r++) {
                float wv = Wv[(size_t)t * CC + half * 128 + r];
                #pragma unroll 8
                for (int u = 0; u < 32; u++) vacc[u] += wv * xs[r][u];
                float wk = Wk[(size_t)c64 * CC + half * 128 + r];
                #pragma unroll
                for (int u = 0; u < 8; u++) kacc[u] += wk * xs[r][part * 8 + u];
            }
        }
        {
            float* vdst = g_v + ((size_t)b * CC + t) * NN + j0;
            #pragma unroll 8
            for (int u = 0; u < 32; u++) vdst[u] = vacc[u];
        }
        #pragma unroll
        for (int u = 0; u < 8; u++) kt[c64][part * 8 + u] = kacc[u];
        if (t < 32) rowmax[t] = -INFINITY;
        __syncthreads();

        // ---- i-loop: q tile, scores, raw write, running row max ----
        for (int it = 0; it < 128; it++) {
            int i0 = it * 32;
            float qacc[8];
            #pragma unroll
            for (int u = 0; u < 8; u++) qacc[u] = bq[c64];
            for (int half = 0; half < 2; half++) {
                __syncthreads();   // previous users of xs / qt done
                for (int r = wid; r < 128; r += 8)
                    xs[r][tx] = xb[(size_t)(half * 128 + r) * NN + i0 + tx];
                __syncthreads();
                for (int r = 0; r < 128; r++) {
                    float wq = Wq[(size_t)c64 * CC + half * 128 + r];
                    #pragma unroll
                    for (int u = 0; u < 8; u++) qacc[u] += wq * xs[r][part * 8 + u];
                }
            }
            #pragma unroll
            for (int u = 0; u < 8; u++) qt[c64][part * 8 + u] = qacc[u];
            __syncthreads();

            float s[4] = {0.f, 0.f, 0.f, 0.f};
            for (int c = 0; c < ACK; c++) {
                float qv = qt[c][tx];
                #pragma unroll
                for (int ss = 0; ss < 4; ss++) s[ss] += qv * kt[c][wid + 8 * ss];
            }
            #pragma unroll
            for (int ss = 0; ss < 4; ss++) {
                int jj = wid + 8 * ss;        // exclusive row ownership per warp
                Pb[(size_t)(j0 + jj) * NN + i0 + tx] = s[ss];
                float m = s[ss];
                for (int o = 16; o > 0; o >>= 1)
                    m = fmaxf(m, __shfl_xor_sync(0xffffffffu, m, o));
                if (tx == 0) rowmax[jj] = fmaxf(rowmax[jj], m);
            }
        }
        __syncthreads();

        // ---- pass 2: exp + row sum (rows just written; L2-hot) ----
        #pragma unroll
        for (int ss = 0; ss < 4; ss++) {
            int jj = wid + 8 * ss;
            float m = rowmax[jj];
            float* row = Pb + (size_t)(j0 + jj) * NN;
            float sum = 0.f;
            for (int i = tx; i < NN; i += 32) {
                float e = expf(row[i] - m);
                row[i] = e;
                sum += e;
            }
            for (int o = 16; o > 0; o >>= 1)
                sum += __shfl_xor_sync(0xffffffffu, sum, o);
            if (tx == 0) rowsum[jj] = sum;
        }
        __syncthreads();

        // ---- pass 3: normalize ----
        #pragma unroll
        for (int ss = 0; ss < 4; ss++) {
            int jj = wid + 8 * ss;
            float inv = 1.0f / rowsum[jj];
            float* row = Pb + (size_t)(j0 + jj) * NN;
            for (int i = tx; i < NN; i += 32) row[i] *= inv;
        }
        __syncthreads();
    }
}

// ---------------------------------------------------------------------
// Kernel B: out[b,c,i] = gamma * sum_j P[b,j,i] * v[b,c,j] + x[b,c,i]
// gamma==0 fast path: MLP-4 vectorized copy out = x.
// ---------------------------------------------------------------------
__global__ void out_kernel(const float* __restrict__ x,
                           const float* __restrict__ gamma,
                           float* __restrict__ out)
{
    float g = gamma[0];
    if (g == 0.0f) {
        const float4* __restrict__ x4 = (const float4*)x;
        float4*       __restrict__ o4 = (float4*)out;
        const int total4 = BB * CC * NN / 4;          // 1,048,576
        int tid = blockIdx.x * blockDim.x + threadIdx.x;
        int nt  = gridDim.x * blockDim.x;             // 262,144 -> exactly 4 each
        for (int i0 = tid; i0 < total4; i0 += 4 * nt) {
            int i1 = i0 + nt, i2 = i0 + 2 * nt, i3 = i0 + 3 * nt;
            float4 a = x4[i0];
            float4 b = (i1 < total4) ? x4[i1] : a;
            float4 c = (i2 < total4) ? x4[i2] : a;
            float4 d = (i3 < total4) ? x4[i3] : a;
            o4[i0] = a;
            if (i1 < total4) o4[i1] = b;
            if (i2 < total4) o4[i2] = c;
            if (i3 < total4) o4[i3] = d;
        }
        return;
    }

    __shared__ float vs[32][32];
    __shared__ float ps[32][33];
    const int tilesC = CC / 32, tilesI = NN / 32;
    const int ntiles = BB * tilesC * tilesI;          // 4096
    int tx = threadIdx.x & 31, ty = threadIdx.x >> 5;
    for (int t = blockIdx.x; t < ntiles; t += gridDim.x) {
        int b  = t / (tilesC * tilesI);
        int rr = t % (tilesC * tilesI);
        int ct = rr / tilesI, it = rr % tilesI;
        int c0 = ct * 32, i0 = it * 32;
        float acc[4] = {0.f, 0.f, 0.f, 0.f};
        for (int j0 = 0; j0 < NN; j0 += 32) {
            for (int rl = ty; rl < 32; rl += 8) {
                vs[rl][tx] = g_v[((size_t)b * CC + c0 + rl) * NN + j0 + tx];
                ps[rl][tx] = g_P[((size_t)b * NN + j0 + rl) * NN + i0 + tx];
            }
            __syncthreads();
            #pragma unroll
            for (int jj = 0; jj < 32; jj++) {
                float pv = ps[jj][tx];
                #pragma unroll
                for (int s = 0; s < 4; s++) acc[s] += vs[ty + 8 * s][jj] * pv;
            }
            __syncthreads();
        }
        #pragma unroll
        for (int s = 0; s < 4; s++) {
            size_t oidx = ((size_t)b * CC + c0 + ty + 8 * s) * NN + i0 + tx;
            out[oidx] = g * acc[s] + x[oidx];
        }
    }
}

// ---------------------------------------------------------------------
extern "C" void kernel_launch(void* const* d_in, const int* in_sizes, int n_in,
                              void* d_out, int out_size)
{
    const float* x     = (const float*)d_in[0];
    const float* Wq    = (const float*)d_in[1];
    const float* bq    = (const float*)d_in[2];
    const float* Wk    = (const float*)d_in[3];
    const float* bk    = (const float*)d_in[4];
    const float* Wv    = (const float*)d_in[5];
    const float* bv    = (const float*)d_in[6];
    const float* gamma = (const float*)d_in[7];
    float* out = (float*)d_out;

    fused_ps_kernel<<<512, 256>>>(x, Wq, bq, Wk, bk, Wv, bv, gamma);
    out_kernel     <<<1024, 256>>>(x, gamma, out);
}